// round 2
// baseline (speedup 1.0000x reference)
#include <cuda_runtime.h>
#include <cstdint>

#define Bq 256
#define Nn 256
#define Dd 1024
#define Ss 1024
#define NT 16   // n-panel depth in main kernel

// Scratch (device globals: allowed; no allocation APIs anywhere)
__device__ float g_A[Bq * Ss];           // state @ Q^T   [256,1024]
__device__ float g_M[Bq * Nn];           // A @ K         [256,256]
__device__ float g_ctx_scratch[Bq * Dd]; // fallback ctx if out holds only W

// ---------------------------------------------------------------------------
__global__ void zero_ctx_kernel(float* __restrict__ ctx) {
    int i = blockIdx.x * blockDim.x + threadIdx.x;
    if (i < Bq * Dd) ctx[i] = 0.0f;
}

// ---------------------------------------------------------------------------
// A[b,s] = sum_k state[b,k] * Q[s,k]   (both K-contiguous)
__global__ void gemm_A_kernel(const float* __restrict__ state,
                              const float* __restrict__ Q) {
    __shared__ float sS[32][33];
    __shared__ float sQ[32][33];
    int tx = threadIdx.x, ty = threadIdx.y;
    int t = ty * 16 + tx;
    int b0 = blockIdx.y * 32, s0 = blockIdx.x * 32;
    float acc00 = 0.f, acc01 = 0.f, acc10 = 0.f, acc11 = 0.f;
    for (int k0 = 0; k0 < Ss; k0 += 32) {
        #pragma unroll
        for (int l = t; l < 1024; l += 256) {
            int r = l >> 5, c = l & 31;
            sS[r][c] = state[(b0 + r) * Ss + k0 + c];
            sQ[r][c] = Q[(s0 + r) * Ss + k0 + c];
        }
        __syncthreads();
        #pragma unroll
        for (int kk = 0; kk < 32; kk++) {
            float a0 = sS[2 * ty][kk],     a1 = sS[2 * ty + 1][kk];
            float q0 = sQ[2 * tx][kk],     q1 = sQ[2 * tx + 1][kk];
            acc00 = fmaf(a0, q0, acc00);
            acc01 = fmaf(a0, q1, acc01);
            acc10 = fmaf(a1, q0, acc10);
            acc11 = fmaf(a1, q1, acc11);
        }
        __syncthreads();
    }
    g_A[(b0 + 2 * ty)     * Ss + s0 + 2 * tx]     = acc00;
    g_A[(b0 + 2 * ty)     * Ss + s0 + 2 * tx + 1] = acc01;
    g_A[(b0 + 2 * ty + 1) * Ss + s0 + 2 * tx]     = acc10;
    g_A[(b0 + 2 * ty + 1) * Ss + s0 + 2 * tx + 1] = acc11;
}

// ---------------------------------------------------------------------------
// M[b,n] = sum_s A[b,s] * K[s,n]
__global__ void gemm_M_kernel(const float* __restrict__ Km) {
    __shared__ float sA[32][33];
    __shared__ float sK[32][33];
    int tx = threadIdx.x, ty = threadIdx.y;
    int t = ty * 16 + tx;
    int b0 = blockIdx.y * 32, n0 = blockIdx.x * 32;
    float acc00 = 0.f, acc01 = 0.f, acc10 = 0.f, acc11 = 0.f;
    for (int kc = 0; kc < Ss; kc += 32) {
        #pragma unroll
        for (int l = t; l < 1024; l += 256) {
            int r = l >> 5, c = l & 31;
            sA[r][c] = g_A[(b0 + r) * Ss + kc + c];
            sK[r][c] = Km[(kc + r) * Nn + n0 + c];
        }
        __syncthreads();
        #pragma unroll
        for (int kk = 0; kk < 32; kk++) {
            float a0 = sA[2 * ty][kk],     a1 = sA[2 * ty + 1][kk];
            float b0v = sK[kk][2 * tx],    b1v = sK[kk][2 * tx + 1];
            acc00 = fmaf(a0, b0v, acc00);
            acc01 = fmaf(a0, b1v, acc01);
            acc10 = fmaf(a1, b0v, acc10);
            acc11 = fmaf(a1, b1v, acc11);
        }
        __syncthreads();
    }
    g_M[(b0 + 2 * ty)     * Nn + n0 + 2 * tx]     = acc00;
    g_M[(b0 + 2 * ty)     * Nn + n0 + 2 * tx + 1] = acc01;
    g_M[(b0 + 2 * ty + 1) * Nn + n0 + 2 * tx]     = acc10;
    g_M[(b0 + 2 * ty + 1) * Nn + n0 + 2 * tx + 1] = acc11;
}

// ---------------------------------------------------------------------------
__device__ __forceinline__ void cp_async16(uint32_t saddr, const void* gptr) {
    asm volatile("cp.async.cg.shared.global [%0], [%1], 16;\n"
                 :: "r"(saddr), "l"(gptr));
}

// Main fused kernel: one CTA = (i, 32 b-rows).
// GEMM over n (panels of NT from SMEM, double-buffered cp.async),
// then in-register softmax over full D row, W store, context partial.
__global__ void __launch_bounds__(512, 1)
attn_main_kernel(const float* __restrict__ FV,
                 float* __restrict__ Wout,
                 float* __restrict__ ctx) {
    extern __shared__ float smem[];
    float* ms = smem + 2 * NT * Dd;   // M slice [32][256]
    const int i   = blockIdx.y;
    const int gb0 = blockIdx.x * 32;
    const int tid = threadIdx.x;
    const int w = tid >> 5, lane = tid & 31;
    const float* FVi = FV + (size_t)i * Nn * Dd;

    // Load this CTA's 32 rows of M into SMEM (kept for entire kernel)
    for (int t2 = tid; t2 < 32 * Nn; t2 += 512)
        ms[t2] = g_M[(gb0 + (t2 >> 8)) * Nn + (t2 & 255)];

    const uint32_t sbase = (uint32_t)__cvta_generic_to_shared(smem);

    // Preload panel 0 (FV[i, 0:NT, :])
    {
        const float4* src = (const float4*)FVi;
        #pragma unroll
        for (int k = 0; k < 8; k++)
            cp_async16(sbase + (uint32_t)(tid + k * 512) * 16, src + tid + k * 512);
        asm volatile("cp.async.commit_group;\n");
    }

    float a0[32], a1[32];
    #pragma unroll
    for (int j = 0; j < 32; j++) { a0[j] = 0.f; a1[j] = 0.f; }
    const int r0 = 2 * w, r1 = 2 * w + 1;

    for (int t = 0; t < Nn / NT; t++) {
        const float* cur = smem + (t & 1) * NT * Dd;
        if (t + 1 < Nn / NT) {
            uint32_t dst = sbase + (uint32_t)(((t + 1) & 1) * NT * Dd) * 4u;
            const float4* src = (const float4*)(FVi + (size_t)(t + 1) * NT * Dd);
            #pragma unroll
            for (int k = 0; k < 8; k++)
                cp_async16(dst + (uint32_t)(tid + k * 512) * 16, src + tid + k * 512);
            asm volatile("cp.async.commit_group;\n");
            asm volatile("cp.async.wait_group 1;\n");
        } else {
            asm volatile("cp.async.wait_group 0;\n");
        }
        __syncthreads();
        #pragma unroll
        for (int nn = 0; nn < NT; nn++) {
            float m0 = ms[r0 * Nn + t * NT + nn];
            float m1 = ms[r1 * Nn + t * NT + nn];
            const float* row = cur + nn * Dd + lane;
            #pragma unroll
            for (int j = 0; j < 32; j++) {
                float v = row[32 * j];          // conflict-free LDS, reused x2
                a0[j] = fmaf(m0, v, a0[j]);
                a1[j] = fmaf(m1, v, a1[j]);
            }
        }
        __syncthreads();
    }

    // ---- softmax over D (each warp owns rows r0, r1; lane holds d = lane+32j)
    float mx0 = a0[0], mx1 = a1[0];
    #pragma unroll
    for (int j = 1; j < 32; j++) { mx0 = fmaxf(mx0, a0[j]); mx1 = fmaxf(mx1, a1[j]); }
    #pragma unroll
    for (int off = 16; off; off >>= 1) {
        mx0 = fmaxf(mx0, __shfl_xor_sync(0xffffffffu, mx0, off));
        mx1 = fmaxf(mx1, __shfl_xor_sync(0xffffffffu, mx1, off));
    }
    float s0 = 0.f, s1 = 0.f;
    #pragma unroll
    for (int j = 0; j < 32; j++) {
        a0[j] = __expf(a0[j] - mx0); s0 += a0[j];
        a1[j] = __expf(a1[j] - mx1); s1 += a1[j];
    }
    #pragma unroll
    for (int off = 16; off; off >>= 1) {
        s0 += __shfl_xor_sync(0xffffffffu, s0, off);
        s1 += __shfl_xor_sync(0xffffffffu, s1, off);
    }
    const float inv0 = 1.f / s0, inv1 = 1.f / s1;

    float* wr0 = Wout + ((size_t)i * Bq + gb0 + r0) * Dd;
    float* wr1 = Wout + ((size_t)i * Bq + gb0 + r1) * Dd;
    const float* fr0 = FVi + (size_t)(gb0 + r0) * Dd;
    const float* fr1 = FVi + (size_t)(gb0 + r1) * Dd;
    float* ctxw = smem;   // reuse fv buffers: [16 warps][Dd]
    #pragma unroll
    for (int j = 0; j < 32; j++) {
        int d = lane + 32 * j;
        float w0 = a0[j] * inv0;
        float w1 = a1[j] * inv1;
        wr0[d] = w0;
        wr1[d] = w1;
        ctxw[w * Dd + d] = fmaf(w0, fr0[d], w1 * fr1[d]);
    }
    __syncthreads();
    for (int d = tid; d < Dd; d += 512) {
        float s = 0.f;
        #pragma unroll
        for (int ww = 0; ww < 16; ww++) s += ctxw[ww * Dd + d];
        atomicAdd(&ctx[(size_t)i * Dd + d], s);
    }
}

// ---------------------------------------------------------------------------
extern "C" void kernel_launch(void* const* d_in, const int* in_sizes, int n_in,
                              void* d_out, int out_size) {
    const float* FV    = (const float*)d_in[0];
    const float* state = (const float*)d_in[1];
    const float* Q     = (const float*)d_in[2];
    const float* Km    = (const float*)d_in[3];
    float* out = (float*)d_out;

    // Output layout: (context [B,D], W [B,B,D]) concatenated. If the harness
    // sized d_out for W only, keep context in device scratch instead.
    const long long wsz = (long long)Bq * Bq * Dd;
    float* ctxp;
    float* Wp;
    if ((long long)out_size == wsz) {
        Wp = out;
        cudaGetSymbolAddress((void**)&ctxp, g_ctx_scratch);
    } else {
        ctxp = out;
        Wp   = out + (size_t)Bq * Dd;
    }

    const int smem_bytes = (2 * NT * Dd + 32 * Nn) * 4;  // 160 KB
    cudaFuncSetAttribute(attn_main_kernel,
                         cudaFuncAttributeMaxDynamicSharedMemorySize, smem_bytes);

    zero_ctx_kernel<<<(Bq * Dd + 511) / 512, 512>>>(ctxp);
    gemm_A_kernel<<<dim3(Ss / 32, Bq / 32), dim3(16, 16)>>>(state, Q);
    gemm_M_kernel<<<dim3(Nn / 32, Bq / 32), dim3(16, 16)>>>(Km);
    attn_main_kernel<<<dim3(Bq / 32, Bq), 512, smem_bytes>>>(FV, Wp, ctxp);
}

// round 3
// speedup vs baseline: 1.3619x; 1.3619x over previous
#include <cuda_runtime.h>
#include <cstdint>

#define Bq 256
#define Nn 256
#define Dd 1024
#define Ss 1024
#define NT 16   // n-panel depth in main kernel

typedef unsigned long long u64t;

// Scratch (device globals: allowed; no allocation APIs anywhere)
__device__ float g_A[Bq * Ss];           // state @ Q^T   [256,1024]
__device__ float g_M[Bq * Nn];           // A @ K         [256,256]
__device__ float g_ctx_scratch[Bq * Dd]; // fallback ctx if out holds only W

// ---------------------------------------------------------------------------
__global__ void zero_ctx_kernel(float* __restrict__ ctx) {
    int i = blockIdx.x * blockDim.x + threadIdx.x;
    if (i < Bq * Dd) ctx[i] = 0.0f;
}

// ---------------------------------------------------------------------------
// A[b,s] = sum_k state[b,k] * Q[s,k]   (both K-contiguous)
__global__ void gemm_A_kernel(const float* __restrict__ state,
                              const float* __restrict__ Q) {
    __shared__ float sS[32][33];
    __shared__ float sQ[32][33];
    int tx = threadIdx.x, ty = threadIdx.y;
    int t = ty * 16 + tx;
    int b0 = blockIdx.y * 32, s0 = blockIdx.x * 32;
    float acc00 = 0.f, acc01 = 0.f, acc10 = 0.f, acc11 = 0.f;
    for (int k0 = 0; k0 < Ss; k0 += 32) {
        #pragma unroll
        for (int l = t; l < 1024; l += 256) {
            int r = l >> 5, c = l & 31;
            sS[r][c] = state[(b0 + r) * Ss + k0 + c];
            sQ[r][c] = Q[(s0 + r) * Ss + k0 + c];
        }
        __syncthreads();
        #pragma unroll
        for (int kk = 0; kk < 32; kk++) {
            float a0 = sS[2 * ty][kk],     a1 = sS[2 * ty + 1][kk];
            float q0 = sQ[2 * tx][kk],     q1 = sQ[2 * tx + 1][kk];
            acc00 = fmaf(a0, q0, acc00);
            acc01 = fmaf(a0, q1, acc01);
            acc10 = fmaf(a1, q0, acc10);
            acc11 = fmaf(a1, q1, acc11);
        }
        __syncthreads();
    }
    g_A[(b0 + 2 * ty)     * Ss + s0 + 2 * tx]     = acc00;
    g_A[(b0 + 2 * ty)     * Ss + s0 + 2 * tx + 1] = acc01;
    g_A[(b0 + 2 * ty + 1) * Ss + s0 + 2 * tx]     = acc10;
    g_A[(b0 + 2 * ty + 1) * Ss + s0 + 2 * tx + 1] = acc11;
}

// ---------------------------------------------------------------------------
// M[b,n] = sum_s A[b,s] * K[s,n]
__global__ void gemm_M_kernel(const float* __restrict__ Km) {
    __shared__ float sA[32][33];
    __shared__ float sK[32][33];
    int tx = threadIdx.x, ty = threadIdx.y;
    int t = ty * 16 + tx;
    int b0 = blockIdx.y * 32, n0 = blockIdx.x * 32;
    float acc00 = 0.f, acc01 = 0.f, acc10 = 0.f, acc11 = 0.f;
    for (int kc = 0; kc < Ss; kc += 32) {
        #pragma unroll
        for (int l = t; l < 1024; l += 256) {
            int r = l >> 5, c = l & 31;
            sA[r][c] = g_A[(b0 + r) * Ss + kc + c];
            sK[r][c] = Km[(kc + r) * Nn + n0 + c];
        }
        __syncthreads();
        #pragma unroll
        for (int kk = 0; kk < 32; kk++) {
            float a0 = sA[2 * ty][kk],     a1 = sA[2 * ty + 1][kk];
            float b0v = sK[kk][2 * tx],    b1v = sK[kk][2 * tx + 1];
            acc00 = fmaf(a0, b0v, acc00);
            acc01 = fmaf(a0, b1v, acc01);
            acc10 = fmaf(a1, b0v, acc10);
            acc11 = fmaf(a1, b1v, acc11);
        }
        __syncthreads();
    }
    g_M[(b0 + 2 * ty)     * Nn + n0 + 2 * tx]     = acc00;
    g_M[(b0 + 2 * ty)     * Nn + n0 + 2 * tx + 1] = acc01;
    g_M[(b0 + 2 * ty + 1) * Nn + n0 + 2 * tx]     = acc10;
    g_M[(b0 + 2 * ty + 1) * Nn + n0 + 2 * tx + 1] = acc11;
}

// ---------------------------------------------------------------------------
__device__ __forceinline__ void cp_async16(uint32_t saddr, const void* gptr) {
    asm volatile("cp.async.cg.shared.global [%0], [%1], 16;\n"
                 :: "r"(saddr), "l"(gptr));
}

// packed f32x2 helpers (SASS FFMA2 — only reachable via PTX fma.rn.f32x2)
__device__ __forceinline__ u64t pack2(float x) {
    u64t r; asm("mov.b64 %0, {%1, %1};" : "=l"(r) : "f"(x)); return r;
}
__device__ __forceinline__ u64t pk2(float x, float y) {
    u64t r; asm("mov.b64 %0, {%1, %2};" : "=l"(r) : "f"(x), "f"(y)); return r;
}
__device__ __forceinline__ float2 up2(u64t a) {
    float2 f; asm("mov.b64 {%0, %1}, %2;" : "=f"(f.x), "=f"(f.y) : "l"(a)); return f;
}
__device__ __forceinline__ void fma2(u64t& d, u64t a, u64t b) {
    asm("fma.rn.f32x2 %0, %1, %2, %0;" : "+l"(d) : "l"(a), "l"(b));
}

// ---------------------------------------------------------------------------
// Main fused kernel: one CTA = (i, 32 b-rows), 16 warps.
// Warp w: row-group rg = w>>2 (rows 8*rg..8*rg+7), d-quarter q = w&3
// (d in [256q, 256q+256)). Each lane: 8 rows x 4 f32x2 accums.
// FFMA2 inner loop: 1 LDS.64 feeds 8 packed FMAs.
__global__ void __launch_bounds__(512, 1)
attn_main_kernel(const float* __restrict__ FV,
                 float* __restrict__ Wout,
                 float* __restrict__ ctx) {
    extern __shared__ float smem[];
    float* ms = smem + 2 * NT * Dd;   // M slice [32][256] during mainloop
    const int i   = blockIdx.y;
    const int gb0 = blockIdx.x * 32;
    const int tid = threadIdx.x;
    const int w = tid >> 5, lane = tid & 31;
    const int rg = w >> 2, q = w & 3;
    const float* FVi = FV + (size_t)i * Nn * Dd;

    // Load this CTA's 32 rows of M into SMEM
    for (int t2 = tid; t2 < 32 * Nn; t2 += 512)
        ms[t2] = g_M[(gb0 + (t2 >> 8)) * Nn + (t2 & 255)];

    const uint32_t sbase = (uint32_t)__cvta_generic_to_shared(smem);

    // Preload panel 0 (FV[i, 0:NT, :])
    {
        const float4* src = (const float4*)FVi;
        #pragma unroll
        for (int k = 0; k < 8; k++)
            cp_async16(sbase + (uint32_t)(tid + k * 512) * 16, src + tid + k * 512);
        asm volatile("cp.async.commit_group;\n");
    }

    u64t acc[8][4];
    #pragma unroll
    for (int r = 0; r < 8; r++)
        #pragma unroll
        for (int jp = 0; jp < 4; jp++) acc[r][jp] = 0ull;

    const int dbase = q * 256 + 2 * lane;

    for (int t = 0; t < Nn / NT; t++) {
        const float* cur = smem + (t & 1) * NT * Dd;
        if (t + 1 < Nn / NT) {
            uint32_t dst = sbase + (uint32_t)(((t + 1) & 1) * NT * Dd) * 4u;
            const float4* src = (const float4*)(FVi + (size_t)(t + 1) * NT * Dd);
            #pragma unroll
            for (int k = 0; k < 8; k++)
                cp_async16(dst + (uint32_t)(tid + k * 512) * 16, src + tid + k * 512);
            asm volatile("cp.async.commit_group;\n");
            asm volatile("cp.async.wait_group 1;\n");
        } else {
            asm volatile("cp.async.wait_group 0;\n");
        }
        __syncthreads();
        #pragma unroll 4
        for (int nn = 0; nn < NT; nn++) {
            u64t mp[8];
            #pragma unroll
            for (int r = 0; r < 8; r++)
                mp[r] = pack2(ms[(8 * rg + r) * Nn + t * NT + nn]);  // broadcast LDS
            const float* row = cur + nn * Dd + dbase;
            u64t v[4];
            #pragma unroll
            for (int jp = 0; jp < 4; jp++)
                v[jp] = *reinterpret_cast<const u64t*>(row + 64 * jp);  // LDS.64
            #pragma unroll
            for (int r = 0; r < 8; r++)
                #pragma unroll
                for (int jp = 0; jp < 4; jp++)
                    fma2(acc[r][jp], mp[r], v[jp]);
        }
        __syncthreads();
    }

    // ---- softmax over full D row (row is split across 4 d-quarter warps)
    float* red  = ms;          // [0:128) warp-partial max, [128:256) partial sum
    float* ctxs = ms + 1024;   // [4 row-groups][Dd] context partials

    float mx[8];
    #pragma unroll
    for (int r = 0; r < 8; r++) {
        float2 f0 = up2(acc[r][0]), f1 = up2(acc[r][1]);
        float2 f2 = up2(acc[r][2]), f3 = up2(acc[r][3]);
        float mm = fmaxf(fmaxf(fmaxf(f0.x, f0.y), fmaxf(f1.x, f1.y)),
                         fmaxf(fmaxf(f2.x, f2.y), fmaxf(f3.x, f3.y)));
        #pragma unroll
        for (int off = 16; off; off >>= 1)
            mm = fmaxf(mm, __shfl_xor_sync(0xffffffffu, mm, off));
        mx[r] = mm;
    }
    if (lane == 0) {
        #pragma unroll
        for (int r = 0; r < 8; r++) red[q * 32 + rg * 8 + r] = mx[r];
    }
    __syncthreads();
    #pragma unroll
    for (int r = 0; r < 8; r++) {
        int idx = rg * 8 + r;
        mx[r] = fmaxf(fmaxf(red[idx], red[32 + idx]),
                      fmaxf(red[64 + idx], red[96 + idx]));
    }
    float sm[8];
    #pragma unroll
    for (int r = 0; r < 8; r++) {
        float s = 0.f;
        #pragma unroll
        for (int jp = 0; jp < 4; jp++) {
            float2 f = up2(acc[r][jp]);
            f.x = __expf(f.x - mx[r]);
            f.y = __expf(f.y - mx[r]);
            s += f.x + f.y;
            acc[r][jp] = pk2(f.x, f.y);   // overwrite with exp values
        }
        #pragma unroll
        for (int off = 16; off; off >>= 1)
            s += __shfl_xor_sync(0xffffffffu, s, off);
        sm[r] = s;
    }
    if (lane == 0) {
        #pragma unroll
        for (int r = 0; r < 8; r++) red[128 + q * 32 + rg * 8 + r] = sm[r];
    }
    __syncthreads();
    #pragma unroll
    for (int r = 0; r < 8; r++) {
        int idx = 128 + rg * 8 + r;
        sm[r] = (red[idx] + red[32 + idx]) + (red[64 + idx] + red[96 + idx]);
    }

    // ---- W store + context partial
    float inv[8];
    #pragma unroll
    for (int r = 0; r < 8; r++) inv[r] = 1.f / sm[r];

    float2 cacc[4];
    #pragma unroll
    for (int jp = 0; jp < 4; jp++) cacc[jp] = make_float2(0.f, 0.f);

    const int growb = gb0 + 8 * rg;
    #pragma unroll
    for (int r = 0; r < 8; r++) {
        const int grow = growb + r;
        float* wr = Wout + ((size_t)i * Bq + grow) * Dd + dbase;
        const float* fr = FVi + (size_t)grow * Dd + dbase;
        #pragma unroll
        for (int jp = 0; jp < 4; jp++) {
            float2 e = up2(acc[r][jp]);
            float w0 = e.x * inv[r], w1 = e.y * inv[r];
            *reinterpret_cast<float2*>(wr + 64 * jp) = make_float2(w0, w1);
            float2 fv = *reinterpret_cast<const float2*>(fr + 64 * jp);
            cacc[jp].x = fmaf(w0, fv.x, cacc[jp].x);
            cacc[jp].y = fmaf(w1, fv.y, cacc[jp].y);
        }
    }
    #pragma unroll
    for (int jp = 0; jp < 4; jp++)
        *reinterpret_cast<float2*>(&ctxs[rg * Dd + dbase + 64 * jp]) = cacc[jp];
    __syncthreads();
    if (rg == 0) {
        #pragma unroll
        for (int jp = 0; jp < 4; jp++) {
            int d = dbase + 64 * jp;
            float2 s0 = *reinterpret_cast<float2*>(&ctxs[d]);
            float2 s1 = *reinterpret_cast<float2*>(&ctxs[Dd + d]);
            float2 s2 = *reinterpret_cast<float2*>(&ctxs[2 * Dd + d]);
            float2 s3 = *reinterpret_cast<float2*>(&ctxs[3 * Dd + d]);
            atomicAdd(&ctx[(size_t)i * Dd + d],     (s0.x + s1.x) + (s2.x + s3.x));
            atomicAdd(&ctx[(size_t)i * Dd + d + 1], (s0.y + s1.y) + (s2.y + s3.y));
        }
    }
}

// ---------------------------------------------------------------------------
extern "C" void kernel_launch(void* const* d_in, const int* in_sizes, int n_in,
                              void* d_out, int out_size) {
    const float* FV    = (const float*)d_in[0];
    const float* state = (const float*)d_in[1];
    const float* Q     = (const float*)d_in[2];
    const float* Km    = (const float*)d_in[3];
    float* out = (float*)d_out;

    // Output layout: (context [B,D], W [B,B,D]) concatenated. If the harness
    // sized d_out for W only, keep context in device scratch instead.
    const long long wsz = (long long)Bq * Bq * Dd;
    float* ctxp;
    float* Wp;
    if ((long long)out_size == wsz) {
        Wp = out;
        cudaGetSymbolAddress((void**)&ctxp, g_ctx_scratch);
    } else {
        ctxp = out;
        Wp   = out + (size_t)Bq * Dd;
    }

    const int smem_bytes = (2 * NT * Dd + 32 * Nn) * 4;  // 160 KB
    cudaFuncSetAttribute(attn_main_kernel,
                         cudaFuncAttributeMaxDynamicSharedMemorySize, smem_bytes);

    zero_ctx_kernel<<<(Bq * Dd + 511) / 512, 512>>>(ctxp);
    gemm_A_kernel<<<dim3(Ss / 32, Bq / 32), dim3(16, 16)>>>(state, Q);
    gemm_M_kernel<<<dim3(Nn / 32, Bq / 32), dim3(16, 16)>>>(Km);
    attn_main_kernel<<<dim3(Bq / 32, Bq), 512, smem_bytes>>>(FV, Wp, ctxp);
}